// round 4
// baseline (speedup 1.0000x reference)
#include <cuda_runtime.h>
#include <cuda_bf16.h>
#include <math.h>

#define BB   128
#define SS   1024
#define TT   257
#define VV   256
#define EE   128
#define HH   512
#define GG   2048
#define DSTEPS 256
#define NCTA 128
#define NTH  256
#define WPAD 514          // weight smem row stride (conflict-free: (2c+k)%32 distinct)

typedef unsigned long long ull;

// ---------------- device globals (no runtime allocation allowed) ----------------
__device__ float g_tabE[VV * GG];
__device__ float g_tabD[VV * GG];
__device__ float g_b1e[GG];
__device__ float g_b1d[GG];
__device__ float g_fcT[HH * VV];                 // [k][v]
__device__ float g_y0T[(size_t)SS * HH * BB];    // 256 MB: y0 transposed per step [s][u][b]
__device__ float g_h0TA[HH * BB], g_h0TB[HH * BB];
__device__ float g_h1TA[HH * BB], g_h1TB[HH * BB];
__device__ float g_h1[BB * HH];                  // plain layout for fc
__device__ int   g_tok[BB];
__device__ int   g_arrive;
__device__ int   g_gen;

// ---------------- small helpers ----------------
__device__ __forceinline__ ull pk2(float lo, float hi) {
    ull r; asm("mov.b64 %0, {%1, %2};" : "=l"(r) : "f"(lo), "f"(hi)); return r;
}
__device__ __forceinline__ void fma2(ull& d, ull a, ull b) {
    asm("fma.rn.f32x2 %0, %1, %2, %0;" : "+l"(d) : "l"(a), "l"(b));
}
__device__ __forceinline__ float2 upk(ull v) {
    float2 f; asm("mov.b64 {%0, %1}, %2;" : "=f"(f.x), "=f"(f.y) : "l"(v)); return f;
}
__device__ __forceinline__ void cp16(float* dst_smem, const float* src) {
    unsigned s = (unsigned)__cvta_generic_to_shared(dst_smem);
    asm volatile("cp.async.cg.shared.global [%0], [%1], 16;" :: "r"(s), "l"(src));
}
#define CP_COMMIT() asm volatile("cp.async.commit_group;")
#define CP_WAIT0()  asm volatile("cp.async.wait_group 0;")
#define CP_WAIT1()  asm volatile("cp.async.wait_group 1;")

// grid barrier: self-resetting generation counter (replay-safe: arrive returns to
// 0 after every barrier; gen is only compared for change, monotonic is fine)
__device__ __forceinline__ void gbar() {
    __syncthreads();
    if (threadIdx.x == 0) {
        volatile int* vgen = &g_gen;
        int gen = *vgen;
        __threadfence();
        int t = atomicAdd(&g_arrive, 1);
        if (t == NCTA - 1) {
            atomicExch(&g_arrive, 0);
            __threadfence();
            atomicAdd(&g_gen, 1);
        } else {
            while (*vgen == gen) { }
        }
        __threadfence();
    }
    __syncthreads();
}

// ---------------- init kernels ----------------
__global__ void table_kernel(float* __restrict__ tab,
                             const float* __restrict__ emb,
                             const float* __restrict__ w_ih,
                             const float* __restrict__ b_ih,
                             const float* __restrict__ b_hh) {
    const int v = blockIdx.x;
    __shared__ float es[EE];
    if (threadIdx.x < EE) es[threadIdx.x] = emb[v * EE + threadIdx.x];
    __syncthreads();
    for (int j = threadIdx.x; j < GG; j += blockDim.x) {
        float a = b_ih[j] + b_hh[j];
        const float* w = w_ih + (size_t)j * EE;
#pragma unroll 8
        for (int e = 0; e < EE; e++) a += es[e] * w[e];
        tab[(size_t)v * GG + j] = a;
    }
}

__global__ void misc_init_kernel(const int* __restrict__ trg,
                                 const float* __restrict__ be_ih1, const float* __restrict__ be_hh1,
                                 const float* __restrict__ bd_ih1, const float* __restrict__ bd_hh1,
                                 const float* __restrict__ fc_w) {
    const int tid = blockIdx.x * blockDim.x + threadIdx.x;
    const int n = gridDim.x * blockDim.x;
    for (int i = tid; i < HH * BB; i += n) {
        g_h0TA[i] = 0.f; g_h0TB[i] = 0.f;
        g_h1TA[i] = 0.f; g_h1TB[i] = 0.f;
    }
    for (int j = tid; j < GG; j += n) {
        g_b1e[j] = be_ih1[j] + be_hh1[j];
        g_b1d[j] = bd_ih1[j] + bd_hh1[j];
    }
    for (int i = tid; i < HH * VV; i += n) {
        int k = i >> 8, v = i & 255;
        g_fcT[i] = fc_w[v * HH + k];
    }
    for (int b = tid; b < BB; b += n) g_tok[b] = trg[b * TT];
}

// ---------------- persistent kernel pieces ----------------
struct Smem {
    float* As;    // double buffer 2 x 64*128
    float* Ws0;   // [16][WPAD]
    float* Wsx;
    float* Wsh;
    float* gbuf;  // [16][130]
    float* cs0;   // [4][128]
    float* cs1;
    int*   tks;   // [128]
};

__device__ __forceinline__ void load_wslice(float* dst, const float* __restrict__ W, int u0) {
    for (int idx = threadIdx.x; idx < 16 * HH; idx += NTH) {
        int c = idx >> 9, k = idx & 511;
        int j = (c >> 2) * HH + u0 + (c & 3);
        dst[c * WPAD + k] = W[(size_t)j * HH + k];
    }
}

__device__ __forceinline__ void stage_chunk(float* dstAs, const float* __restrict__ srcT) {
#pragma unroll
    for (int i = 0; i < 8; i++) {
        int idx = i * NTH + threadIdx.x;          // 2048 x 16B = 64k x 128b floats
        cp16(dstAs + idx * 4, srcT + idx * 4);
    }
}

__device__ __forceinline__ void comp_chunk(const float* __restrict__ As,
                                           const float* __restrict__ wp,
                                           ull acc[4], int r0) {
#pragma unroll 16
    for (int k = 0; k < 64; k++) {
        const ulonglong2* ap = (const ulonglong2*)(As + k * 128 + r0);
        ulonglong2 q0 = ap[0];
        ulonglong2 q1 = ap[1];
        float w = wp[k];
        ull w2 = pk2(w, w);
        fma2(acc[0], q0.x, w2);
        fma2(acc[1], q0.y, w2);
        fma2(acc[2], q1.x, w2);
        fma2(acc[3], q1.y, w2);
    }
}

// 128x16 tile GEMM over K=512: acc += srcT^T(128x512 as [k][b]) * Wsm col c
__device__ __forceinline__ void mma512(const float* __restrict__ srcT,
                                       const float* __restrict__ Wc,
                                       float* As, ull acc[4], int r0, int c) {
    const float* wp = Wc + c * WPAD;
    stage_chunk(As, srcT);
    CP_COMMIT();
#pragma unroll 1
    for (int ch = 0; ch < 8; ch++) {
        float* cur = As + (ch & 1) * 8192;
        if (ch < 7) {
            stage_chunk(As + ((ch + 1) & 1) * 8192, srcT + (ch + 1) * 8192);
            CP_COMMIT();
            CP_WAIT1();
        } else {
            CP_WAIT0();
        }
        __syncthreads();
        comp_chunk(cur, wp + ch * 64, acc, r0);
        __syncthreads();
    }
}

template<bool HAS_TOK, bool HAS_X, bool WRITE_PLAIN>
__device__ __forceinline__ void lstm_step_dev(const Smem& sm,
                                              const float* __restrict__ tab,      // HAS_TOK
                                              const float* __restrict__ bias,     // !HAS_TOK
                                              const float* __restrict__ xT,       // HAS_X
                                              const float* __restrict__ Wx,
                                              const float* __restrict__ hT,
                                              const float* __restrict__ Wh,
                                              float* __restrict__ cs,
                                              float* __restrict__ hT_out,
                                              float* __restrict__ h_plain,
                                              int u0) {
    const int tid = threadIdx.x;
    const int rg = tid >> 4, cg = tid & 15;
    const int r0 = rg * 8;
    const int jc = (cg >> 2) * HH + u0 + (cg & 3);

    ull acc[4];
    if (HAS_TOK) {
#pragma unroll
        for (int rp = 0; rp < 4; rp++) {
            int ta = sm.tks[r0 + 2 * rp];
            int tb = sm.tks[r0 + 2 * rp + 1];
            acc[rp] = pk2(tab[(size_t)ta * GG + jc], tab[(size_t)tb * GG + jc]);
        }
    } else {
        float bv = bias[jc];
        ull b2 = pk2(bv, bv);
#pragma unroll
        for (int rp = 0; rp < 4; rp++) acc[rp] = b2;
    }

    if (HAS_X) mma512(xT, Wx, sm.As, acc, r0, cg);
    mma512(hT, Wh, sm.As, acc, r0, cg);

#pragma unroll
    for (int rp = 0; rp < 4; rp++)
        *(ull*)&sm.gbuf[cg * 130 + r0 + 2 * rp] = acc[rp];
    __syncthreads();

    // state update: thread -> (b = tid&127, uu = tid>>7 and +2)
    const int b = tid & 127;
    const int uu0 = tid >> 7;
#pragma unroll
    for (int p = 0; p < 2; p++) {
        int uu = uu0 + p * 2;
        float gi = sm.gbuf[(0 * 4 + uu) * 130 + b];
        float gf = sm.gbuf[(1 * 4 + uu) * 130 + b];
        float gg = sm.gbuf[(2 * 4 + uu) * 130 + b];
        float go = sm.gbuf[(3 * 4 + uu) * 130 + b];
        float cold = cs[uu * 128 + b];
        float ig = 1.f / (1.f + expf(-gi));
        float fg = 1.f / (1.f + expf(-gf));
        float og = 1.f / (1.f + expf(-go));
        float cn = fg * cold + ig * tanhf(gg);
        float hn = og * tanhf(cn);
        cs[uu * 128 + b] = cn;
        hT_out[(u0 + uu) * 128 + b] = hn;
        if (WRITE_PLAIN) h_plain[b * HH + u0 + uu] = hn;
    }
    __syncthreads();
}

__device__ __forceinline__ void fc_step(const Smem& sm, int t,
                                        const float* __restrict__ fc_b,
                                        float* __restrict__ out) {
    const int b = blockIdx.x;
    const int tid = threadIdx.x;
    float* h1s = sm.gbuf;             // 512
    float* rv = sm.gbuf + 512;        // 256
    int*   ri = (int*)(sm.gbuf + 512 + 256);

    *(float2*)&h1s[tid * 2] = *(const float2*)&g_h1[b * HH + tid * 2];
    __syncthreads();

    float acc = fc_b[tid];
#pragma unroll 8
    for (int k = 0; k < HH; k++) acc += h1s[k] * g_fcT[k * VV + tid];
    out[((size_t)b * DSTEPS + t) * VV + tid] = acc;
    rv[tid] = acc; ri[tid] = tid;
    __syncthreads();
    for (int offs = 128; offs > 0; offs >>= 1) {
        if (tid < offs) {
            float o = rv[tid + offs]; int oi = ri[tid + offs];
            if (o > rv[tid] || (o == rv[tid] && oi < ri[tid])) { rv[tid] = o; ri[tid] = oi; }
        }
        __syncthreads();
    }
    if (tid == 0) g_tok[b] = ri[0];
    __syncthreads();
}

// ---------------- the persistent kernel ----------------
__global__ void __launch_bounds__(NTH, 1)
seq2seq_persistent(const int* __restrict__ src,
                   const float* __restrict__ eWhh0,
                   const float* __restrict__ eWih1, const float* __restrict__ eWhh1,
                   const float* __restrict__ dWhh0,
                   const float* __restrict__ dWih1, const float* __restrict__ dWhh1,
                   const float* __restrict__ fc_b,
                   float* __restrict__ out) {
    extern __shared__ float smraw[];
    Smem sm;
    sm.As  = smraw;                    // 16384
    sm.Ws0 = smraw + 16384;            // 16*514
    sm.Wsx = sm.Ws0 + 16 * WPAD;
    sm.Wsh = sm.Wsx + 16 * WPAD;
    sm.gbuf = sm.Wsh + 16 * WPAD;      // 16*130
    sm.cs0 = sm.gbuf + 16 * 130;       // 512
    sm.cs1 = sm.cs0 + 512;
    sm.tks = (int*)(sm.cs1 + 512);     // 128

    const int tid = threadIdx.x;
    const int u0 = blockIdx.x * 4;

    // ===== encoder layer 0 =====
    load_wslice(sm.Ws0, eWhh0, u0);
    for (int i = tid; i < 512; i += NTH) sm.cs0[i] = 0.f;
    __syncthreads();
    const float* hcur = g_h0TA;                      // zeros from misc_init
    for (int s = 0; s < SS; s++) {
        if (tid < BB) sm.tks[tid] = src[tid * SS + s];
        __syncthreads();
        float* yT = g_y0T + (size_t)s * (HH * BB);
        lstm_step_dev<true, false, false>(sm, g_tabE, nullptr, nullptr, nullptr,
                                          hcur, sm.Ws0, sm.cs0, yT, nullptr, u0);
        hcur = yT;
        gbar();
    }

    // ===== encoder layer 1 =====
    load_wslice(sm.Wsx, eWih1, u0);
    load_wslice(sm.Wsh, eWhh1, u0);
    for (int i = tid; i < 512; i += NTH) sm.cs1[i] = 0.f;
    __syncthreads();
    float* h1cur = g_h1TA;                           // zeros
    float* h1nxt = g_h1TB;
    for (int s = 0; s < SS; s++) {
        const float* xT = g_y0T + (size_t)s * (HH * BB);
        lstm_step_dev<false, true, false>(sm, nullptr, g_b1e, xT, sm.Wsx,
                                          h1cur, sm.Wsh, sm.cs1, h1nxt, nullptr, u0);
        float* tt = h1cur; h1cur = h1nxt; h1nxt = tt;
        gbar();
    }

    // ===== decoder =====
    load_wslice(sm.Ws0, dWhh0, u0);
    load_wslice(sm.Wsx, dWih1, u0);
    load_wslice(sm.Wsh, dWhh1, u0);
    __syncthreads();
    const float* h0cur = g_y0T + (size_t)(SS - 1) * (HH * BB);  // encoder L0 final h
    float* h0bufs[2] = { g_h0TA, g_h0TB };
    for (int t = 0; t < DSTEPS; t++) {
        if (tid < BB) sm.tks[tid] = g_tok[tid];
        __syncthreads();
        float* h0nxt = h0bufs[t & 1];
        lstm_step_dev<true, false, false>(sm, g_tabD, nullptr, nullptr, nullptr,
                                          h0cur, sm.Ws0, sm.cs0, h0nxt, nullptr, u0);
        gbar();
        lstm_step_dev<false, true, true>(sm, nullptr, g_b1d, h0nxt, sm.Wsx,
                                         h1cur, sm.Wsh, sm.cs1, h1nxt, g_h1, u0);
        gbar();
        fc_step(sm, t, fc_b, out);
        gbar();
        h0cur = h0nxt;
        float* tt = h1cur; h1cur = h1nxt; h1nxt = tt;
    }
}

// ---------------- host launch ----------------
extern "C" void kernel_launch(void* const* d_in, const int* in_sizes, int n_in,
                              void* d_out, int out_size) {
    const int*   src       = (const int*)d_in[0];
    const int*   trg       = (const int*)d_in[1];
    const float* enc_emb   = (const float*)d_in[2];
    const float* enc_w_ih0 = (const float*)d_in[3];
    const float* enc_w_hh0 = (const float*)d_in[4];
    const float* enc_b_ih0 = (const float*)d_in[5];
    const float* enc_b_hh0 = (const float*)d_in[6];
    const float* enc_w_ih1 = (const float*)d_in[7];
    const float* enc_w_hh1 = (const float*)d_in[8];
    const float* enc_b_ih1 = (const float*)d_in[9];
    const float* enc_b_hh1 = (const float*)d_in[10];
    const float* dec_emb   = (const float*)d_in[11];
    const float* dec_w_ih0 = (const float*)d_in[12];
    const float* dec_w_hh0 = (const float*)d_in[13];
    const float* dec_b_ih0 = (const float*)d_in[14];
    const float* dec_b_hh0 = (const float*)d_in[15];
    const float* dec_w_ih1 = (const float*)d_in[16];
    const float* dec_w_hh1 = (const float*)d_in[17];
    const float* dec_b_ih1 = (const float*)d_in[18];
    const float* dec_b_hh1 = (const float*)d_in[19];
    const float* fc_w      = (const float*)d_in[20];
    const float* fc_b      = (const float*)d_in[21];
    float* out = (float*)d_out;

    float* tabE; cudaGetSymbolAddress((void**)&tabE, g_tabE);
    float* tabD; cudaGetSymbolAddress((void**)&tabD, g_tabD);

    static int smem_set = 0;
    const int SMEM_BYTES = (16384 + 3 * 16 * WPAD + 16 * 130 + 512 + 512 + 128) * 4;
    if (!smem_set) {
        cudaFuncSetAttribute(seq2seq_persistent,
                             cudaFuncAttributeMaxDynamicSharedMemorySize, SMEM_BYTES);
        smem_set = 1;
    }

    table_kernel<<<VV, 256>>>(tabE, enc_emb, enc_w_ih0, enc_b_ih0, enc_b_hh0);
    table_kernel<<<VV, 256>>>(tabD, dec_emb, dec_w_ih0, dec_b_ih0, dec_b_hh0);
    misc_init_kernel<<<256, 256>>>(trg, enc_b_ih1, enc_b_hh1, dec_b_ih1, dec_b_hh1, fc_w);

    seq2seq_persistent<<<NCTA, NTH, SMEM_BYTES>>>(
        src, enc_w_hh0, enc_w_ih1, enc_w_hh1,
        dec_w_hh0, dec_w_ih1, dec_w_hh1, fc_b, out);

    (void)in_sizes; (void)n_in; (void)out_size;
}

// round 5
// speedup vs baseline: 1.0005x; 1.0005x over previous
#include <cuda_runtime.h>
#include <cuda_bf16.h>
#include <math.h>

#define BB   128
#define SS   1024
#define TT   257
#define VV   256
#define EE   128
#define HH   512
#define GG   2048
#define DSTEPS 256
#define NCTA 128
#define NTH  256
#define WPAD 514          // weight smem row stride (conflict-free: (2c+k)%32 distinct)

typedef unsigned long long ull;

// ---------------- device globals (no runtime allocation allowed) ----------------
__device__ float g_tabE[VV * GG];
__device__ float g_tabD[VV * GG];
__device__ float g_b1e[GG];
__device__ float g_b1d[GG];
__device__ float g_fcT[HH * VV];                 // [k][v]
__device__ float g_y0T[(size_t)SS * HH * BB];    // 256 MB: y0 transposed per step [s][u][b]
__device__ float g_h0TA[HH * BB], g_h0TB[HH * BB];
__device__ float g_h1TA[HH * BB], g_h1TB[HH * BB];
__device__ float g_h1[BB * HH];                  // plain layout for fc
__device__ int   g_tok[BB];
__device__ int   g_arrive;
__device__ int   g_gen;

// ---------------- small helpers ----------------
__device__ __forceinline__ ull pk2(float lo, float hi) {
    ull r; asm("mov.b64 %0, {%1, %2};" : "=l"(r) : "f"(lo), "f"(hi)); return r;
}
__device__ __forceinline__ void fma2(ull& d, ull a, ull b) {
    asm("fma.rn.f32x2 %0, %1, %2, %0;" : "+l"(d) : "l"(a), "l"(b));
}
__device__ __forceinline__ float2 upk(ull v) {
    float2 f; asm("mov.b64 {%0, %1}, %2;" : "=f"(f.x), "=f"(f.y) : "l"(v)); return f;
}
__device__ __forceinline__ void cp16(float* dst_smem, const float* src) {
    unsigned s = (unsigned)__cvta_generic_to_shared(dst_smem);
    asm volatile("cp.async.cg.shared.global [%0], [%1], 16;" :: "r"(s), "l"(src));
}
#define CP_COMMIT() asm volatile("cp.async.commit_group;")
#define CP_WAIT0()  asm volatile("cp.async.wait_group 0;")
#define CP_WAIT1()  asm volatile("cp.async.wait_group 1;")

// grid barrier: self-resetting generation counter (replay-safe: arrive returns to
// 0 after every barrier; gen is only compared for change, monotonic is fine)
__device__ __forceinline__ void gbar() {
    __syncthreads();
    if (threadIdx.x == 0) {
        volatile int* vgen = &g_gen;
        int gen = *vgen;
        __threadfence();
        int t = atomicAdd(&g_arrive, 1);
        if (t == NCTA - 1) {
            atomicExch(&g_arrive, 0);
            __threadfence();
            atomicAdd(&g_gen, 1);
        } else {
            while (*vgen == gen) { }
        }
        __threadfence();
    }
    __syncthreads();
}

// ---------------- init kernels ----------------
__global__ void table_kernel(float* __restrict__ tab,
                             const float* __restrict__ emb,
                             const float* __restrict__ w_ih,
                             const float* __restrict__ b_ih,
                             const float* __restrict__ b_hh) {
    const int v = blockIdx.x;
    __shared__ float es[EE];
    if (threadIdx.x < EE) es[threadIdx.x] = emb[v * EE + threadIdx.x];
    __syncthreads();
    for (int j = threadIdx.x; j < GG; j += blockDim.x) {
        float a = b_ih[j] + b_hh[j];
        const float* w = w_ih + (size_t)j * EE;
#pragma unroll 8
        for (int e = 0; e < EE; e++) a += es[e] * w[e];
        tab[(size_t)v * GG + j] = a;
    }
}

__global__ void misc_init_kernel(const int* __restrict__ trg,
                                 const float* __restrict__ be_ih1, const float* __restrict__ be_hh1,
                                 const float* __restrict__ bd_ih1, const float* __restrict__ bd_hh1,
                                 const float* __restrict__ fc_w) {
    const int tid = blockIdx.x * blockDim.x + threadIdx.x;
    const int n = gridDim.x * blockDim.x;
    for (int i = tid; i < HH * BB; i += n) {
        g_h0TA[i] = 0.f; g_h0TB[i] = 0.f;
        g_h1TA[i] = 0.f; g_h1TB[i] = 0.f;
    }
    for (int j = tid; j < GG; j += n) {
        g_b1e[j] = be_ih1[j] + be_hh1[j];
        g_b1d[j] = bd_ih1[j] + bd_hh1[j];
    }
    for (int i = tid; i < HH * VV; i += n) {
        int k = i >> 8, v = i & 255;
        g_fcT[i] = fc_w[v * HH + k];
    }
    for (int b = tid; b < BB; b += n) g_tok[b] = trg[b * TT];
}

// ---------------- persistent kernel pieces ----------------
struct Smem {
    float* As;    // double buffer 2 x 64*128
    float* Ws0;   // [16][WPAD]
    float* Wsx;
    float* Wsh;
    float* gbuf;  // [16][130]
    float* cs0;   // [4][128]
    float* cs1;
    int*   tks;   // [128]
};

__device__ __forceinline__ void load_wslice(float* dst, const float* __restrict__ W, int u0) {
    for (int idx = threadIdx.x; idx < 16 * HH; idx += NTH) {
        int c = idx >> 9, k = idx & 511;
        int j = (c >> 2) * HH + u0 + (c & 3);
        dst[c * WPAD + k] = W[(size_t)j * HH + k];
    }
}

__device__ __forceinline__ void stage_chunk(float* dstAs, const float* __restrict__ srcT) {
#pragma unroll
    for (int i = 0; i < 8; i++) {
        int idx = i * NTH + threadIdx.x;          // 2048 x 16B = 64k x 128b floats
        cp16(dstAs + idx * 4, srcT + idx * 4);
    }
}

__device__ __forceinline__ void comp_chunk(const float* __restrict__ As,
                                           const float* __restrict__ wp,
                                           ull acc[4], int r0) {
#pragma unroll 16
    for (int k = 0; k < 64; k++) {
        const ulonglong2* ap = (const ulonglong2*)(As + k * 128 + r0);
        ulonglong2 q0 = ap[0];
        ulonglong2 q1 = ap[1];
        float w = wp[k];
        ull w2 = pk2(w, w);
        fma2(acc[0], q0.x, w2);
        fma2(acc[1], q0.y, w2);
        fma2(acc[2], q1.x, w2);
        fma2(acc[3], q1.y, w2);
    }
}

// 128x16 tile GEMM over K=512: acc += srcT^T(128x512 as [k][b]) * Wsm col c
__device__ __forceinline__ void mma512(const float* __restrict__ srcT,
                                       const float* __restrict__ Wc,
                                       float* As, ull acc[4], int r0, int c) {
    const float* wp = Wc + c * WPAD;
    stage_chunk(As, srcT);
    CP_COMMIT();
#pragma unroll 1
    for (int ch = 0; ch < 8; ch++) {
        float* cur = As + (ch & 1) * 8192;
        if (ch < 7) {
            stage_chunk(As + ((ch + 1) & 1) * 8192, srcT + (ch + 1) * 8192);
            CP_COMMIT();
            CP_WAIT1();
        } else {
            CP_WAIT0();
        }
        __syncthreads();
        comp_chunk(cur, wp + ch * 64, acc, r0);
        __syncthreads();
    }
}

template<bool HAS_TOK, bool HAS_X, bool WRITE_PLAIN>
__device__ __forceinline__ void lstm_step_dev(const Smem& sm,
                                              const float* __restrict__ tab,      // HAS_TOK
                                              const float* __restrict__ bias,     // !HAS_TOK
                                              const float* __restrict__ xT,       // HAS_X
                                              const float* __restrict__ Wx,
                                              const float* __restrict__ hT,
                                              const float* __restrict__ Wh,
                                              float* __restrict__ cs,
                                              float* __restrict__ hT_out,
                                              float* __restrict__ h_plain,
                                              int u0) {
    const int tid = threadIdx.x;
    const int rg = tid >> 4, cg = tid & 15;
    const int r0 = rg * 8;
    const int jc = (cg >> 2) * HH + u0 + (cg & 3);

    ull acc[4];
    if (HAS_TOK) {
#pragma unroll
        for (int rp = 0; rp < 4; rp++) {
            int ta = sm.tks[r0 + 2 * rp];
            int tb = sm.tks[r0 + 2 * rp + 1];
            acc[rp] = pk2(tab[(size_t)ta * GG + jc], tab[(size_t)tb * GG + jc]);
        }
    } else {
        float bv = bias[jc];
        ull b2 = pk2(bv, bv);
#pragma unroll
        for (int rp = 0; rp < 4; rp++) acc[rp] = b2;
    }

    if (HAS_X) mma512(xT, Wx, sm.As, acc, r0, cg);
    mma512(hT, Wh, sm.As, acc, r0, cg);

#pragma unroll
    for (int rp = 0; rp < 4; rp++)
        *(ull*)&sm.gbuf[cg * 130 + r0 + 2 * rp] = acc[rp];
    __syncthreads();

    // state update: thread -> (b = tid&127, uu = tid>>7 and +2)
    const int b = tid & 127;
    const int uu0 = tid >> 7;
#pragma unroll
    for (int p = 0; p < 2; p++) {
        int uu = uu0 + p * 2;
        float gi = sm.gbuf[(0 * 4 + uu) * 130 + b];
        float gf = sm.gbuf[(1 * 4 + uu) * 130 + b];
        float gg = sm.gbuf[(2 * 4 + uu) * 130 + b];
        float go = sm.gbuf[(3 * 4 + uu) * 130 + b];
        float cold = cs[uu * 128 + b];
        float ig = 1.f / (1.f + expf(-gi));
        float fg = 1.f / (1.f + expf(-gf));
        float og = 1.f / (1.f + expf(-go));
        float cn = fg * cold + ig * tanhf(gg);
        float hn = og * tanhf(cn);
        cs[uu * 128 + b] = cn;
        hT_out[(u0 + uu) * 128 + b] = hn;
        if (WRITE_PLAIN) h_plain[b * HH + u0 + uu] = hn;
    }
    __syncthreads();
}

__device__ __forceinline__ void fc_step(const Smem& sm, int t,
                                        const float* __restrict__ fc_b,
                                        float* __restrict__ out) {
    const int b = blockIdx.x;
    const int tid = threadIdx.x;
    float* h1s = sm.gbuf;             // 512
    float* rv = sm.gbuf + 512;        // 256
    int*   ri = (int*)(sm.gbuf + 512 + 256);

    *(float2*)&h1s[tid * 2] = *(const float2*)&g_h1[b * HH + tid * 2];
    __syncthreads();

    float acc = fc_b[tid];
#pragma unroll 8
    for (int k = 0; k < HH; k++) acc += h1s[k] * g_fcT[k * VV + tid];
    out[((size_t)b * DSTEPS + t) * VV + tid] = acc;
    rv[tid] = acc; ri[tid] = tid;
    __syncthreads();
    for (int offs = 128; offs > 0; offs >>= 1) {
        if (tid < offs) {
            float o = rv[tid + offs]; int oi = ri[tid + offs];
            if (o > rv[tid] || (o == rv[tid] && oi < ri[tid])) { rv[tid] = o; ri[tid] = oi; }
        }
        __syncthreads();
    }
    if (tid == 0) g_tok[b] = ri[0];
    __syncthreads();
}

// ---------------- the persistent kernel ----------------
__global__ void __launch_bounds__(NTH, 1)
seq2seq_persistent(const int* __restrict__ src,
                   const float* __restrict__ eWhh0,
                   const float* __restrict__ eWih1, const float* __restrict__ eWhh1,
                   const float* __restrict__ dWhh0,
                   const float* __restrict__ dWih1, const float* __restrict__ dWhh1,
                   const float* __restrict__ fc_b,
                   float* __restrict__ out) {
    extern __shared__ float smraw[];
    Smem sm;
    sm.As  = smraw;                    // 16384
    sm.Ws0 = smraw + 16384;            // 16*514
    sm.Wsx = sm.Ws0 + 16 * WPAD;
    sm.Wsh = sm.Wsx + 16 * WPAD;
    sm.gbuf = sm.Wsh + 16 * WPAD;      // 16*130
    sm.cs0 = sm.gbuf + 16 * 130;       // 512
    sm.cs1 = sm.cs0 + 512;
    sm.tks = (int*)(sm.cs1 + 512);     // 128

    const int tid = threadIdx.x;
    const int u0 = blockIdx.x * 4;

    // ===== encoder layer 0 =====
    load_wslice(sm.Ws0, eWhh0, u0);
    for (int i = tid; i < 512; i += NTH) sm.cs0[i] = 0.f;
    __syncthreads();
    const float* hcur = g_h0TA;                      // zeros from misc_init
    for (int s = 0; s < SS; s++) {
        if (tid < BB) sm.tks[tid] = src[tid * SS + s];
        __syncthreads();
        float* yT = g_y0T + (size_t)s * (HH * BB);
        lstm_step_dev<true, false, false>(sm, g_tabE, nullptr, nullptr, nullptr,
                                          hcur, sm.Ws0, sm.cs0, yT, nullptr, u0);
        hcur = yT;
        gbar();
    }

    // ===== encoder layer 1 =====
    load_wslice(sm.Wsx, eWih1, u0);
    load_wslice(sm.Wsh, eWhh1, u0);
    for (int i = tid; i < 512; i += NTH) sm.cs1[i] = 0.f;
    __syncthreads();
    float* h1cur = g_h1TA;                           // zeros
    float* h1nxt = g_h1TB;
    for (int s = 0; s < SS; s++) {
        const float* xT = g_y0T + (size_t)s * (HH * BB);
        lstm_step_dev<false, true, false>(sm, nullptr, g_b1e, xT, sm.Wsx,
                                          h1cur, sm.Wsh, sm.cs1, h1nxt, nullptr, u0);
        float* tt = h1cur; h1cur = h1nxt; h1nxt = tt;
        gbar();
    }

    // ===== decoder =====
    load_wslice(sm.Ws0, dWhh0, u0);
    load_wslice(sm.Wsx, dWih1, u0);
    load_wslice(sm.Wsh, dWhh1, u0);
    __syncthreads();
    const float* h0cur = g_y0T + (size_t)(SS - 1) * (HH * BB);  // encoder L0 final h
    float* h0bufs[2] = { g_h0TA, g_h0TB };
    for (int t = 0; t < DSTEPS; t++) {
        if (tid < BB) sm.tks[tid] = g_tok[tid];
        __syncthreads();
        float* h0nxt = h0bufs[t & 1];
        lstm_step_dev<true, false, false>(sm, g_tabD, nullptr, nullptr, nullptr,
                                          h0cur, sm.Ws0, sm.cs0, h0nxt, nullptr, u0);
        gbar();
        lstm_step_dev<false, true, true>(sm, nullptr, g_b1d, h0nxt, sm.Wsx,
                                         h1cur, sm.Wsh, sm.cs1, h1nxt, g_h1, u0);
        gbar();
        fc_step(sm, t, fc_b, out);
        gbar();
        h0cur = h0nxt;
        float* tt = h1cur; h1cur = h1nxt; h1nxt = tt;
    }
}

// ---------------- host launch ----------------
extern "C" void kernel_launch(void* const* d_in, const int* in_sizes, int n_in,
                              void* d_out, int out_size) {
    const int*   src       = (const int*)d_in[0];
    const int*   trg       = (const int*)d_in[1];
    const float* enc_emb   = (const float*)d_in[2];
    const float* enc_w_ih0 = (const float*)d_in[3];
    const float* enc_w_hh0 = (const float*)d_in[4];
    const float* enc_b_ih0 = (const float*)d_in[5];
    const float* enc_b_hh0 = (const float*)d_in[6];
    const float* enc_w_ih1 = (const float*)d_in[7];
    const float* enc_w_hh1 = (const float*)d_in[8];
    const float* enc_b_ih1 = (const float*)d_in[9];
    const float* enc_b_hh1 = (const float*)d_in[10];
    const float* dec_emb   = (const float*)d_in[11];
    const float* dec_w_ih0 = (const float*)d_in[12];
    const float* dec_w_hh0 = (const float*)d_in[13];
    const float* dec_b_ih0 = (const float*)d_in[14];
    const float* dec_b_hh0 = (const float*)d_in[15];
    const float* dec_w_ih1 = (const float*)d_in[16];
    const float* dec_w_hh1 = (const float*)d_in[17];
    const float* dec_b_ih1 = (const float*)d_in[18];
    const float* dec_b_hh1 = (const float*)d_in[19];
    const float* fc_w      = (const float*)d_in[20];
    const float* fc_b      = (const float*)d_in[21];
    float* out = (float*)d_out;

    float* tabE; cudaGetSymbolAddress((void**)&tabE, g_tabE);
    float* tabD; cudaGetSymbolAddress((void**)&tabD, g_tabD);

    static int smem_set = 0;
    const int SMEM_BYTES = (16384 + 3 * 16 * WPAD + 16 * 130 + 512 + 512 + 128) * 4;
    if (!smem_set) {
        cudaFuncSetAttribute(seq2seq_persistent,
                             cudaFuncAttributeMaxDynamicSharedMemorySize, SMEM_BYTES);
        smem_set = 1;
    }

    table_kernel<<<VV, 256>>>(tabE, enc_emb, enc_w_ih0, enc_b_ih0, enc_b_hh0);
    table_kernel<<<VV, 256>>>(tabD, dec_emb, dec_w_ih0, dec_b_ih0, dec_b_hh0);
    misc_init_kernel<<<256, 256>>>(trg, enc_b_ih1, enc_b_hh1, dec_b_ih1, dec_b_hh1, fc_w);

    seq2seq_persistent<<<NCTA, NTH, SMEM_BYTES>>>(
        src, enc_w_hh0, enc_w_ih1, enc_w_hh1,
        dec_w_hh0, dec_w_ih1, dec_w_hh1, fc_b, out);

    (void)in_sizes; (void)n_in; (void)out_size;
}

// round 6
// speedup vs baseline: 1.0468x; 1.0462x over previous
#include <cuda_runtime.h>
#include <cuda_bf16.h>
#include <math.h>

#define BB   128
#define SS   1024
#define TT   257
#define VV   256
#define EE   128
#define HH   512
#define GG   2048
#define DSTEPS 256
#define NCTA 128
#define NTH  256
#define WPAD 516          // weight smem row stride, float4-load friendly
#define HB   (HH * BB)

typedef unsigned long long ull;

// ---------------- device globals ----------------
__device__ float g_tabE[VV * GG];
__device__ float g_tabD[VV * GG];
__device__ float g_b1e[GG];
__device__ float g_b1d[GG];
__device__ float g_fcT[HH * VV];                 // [k][v]
__device__ float g_y0T[(size_t)SS * HB];         // encoder L0 outputs, [s][u][b]
__device__ float g_h0TA[HB], g_h0TB[HB];
__device__ float g_h1TA[HB], g_h1TB[HB];
__device__ float g_h1[BB * HH];                  // plain layout for fc
__device__ int   g_tok[BB];
__device__ int   g_arrive;
__device__ int   g_gen;

// ---------------- helpers ----------------
__device__ __forceinline__ ull pk2(float lo, float hi) {
    ull r; asm("mov.b64 %0, {%1, %2};" : "=l"(r) : "f"(lo), "f"(hi)); return r;
}
__device__ __forceinline__ void fma2(ull& d, ull a, ull b) {
    asm("fma.rn.f32x2 %0, %1, %2, %0;" : "+l"(d) : "l"(a), "l"(b));
}
__device__ __forceinline__ void cp16(float* dst_smem, const float* src) {
    unsigned s = (unsigned)__cvta_generic_to_shared(dst_smem);
    asm volatile("cp.async.cg.shared.global [%0], [%1], 16;" :: "r"(s), "l"(src));
}
#define CP_COMMIT() asm volatile("cp.async.commit_group;")
#define CP_WAIT0()  asm volatile("cp.async.wait_group 0;")
#define CP_WAIT1()  asm volatile("cp.async.wait_group 1;")

__device__ __forceinline__ void gbar() {
    __syncthreads();
    if (threadIdx.x == 0) {
        volatile int* vgen = &g_gen;
        int gen = *vgen;
        __threadfence();
        int t = atomicAdd(&g_arrive, 1);
        if (t == NCTA - 1) {
            atomicExch(&g_arrive, 0);
            __threadfence();
            atomicAdd(&g_gen, 1);
        } else {
            while (*vgen == gen) { }
        }
        __threadfence();
    }
    __syncthreads();
}

// ---------------- init kernels ----------------
__global__ void table_kernel(float* __restrict__ tab,
                             const float* __restrict__ emb,
                             const float* __restrict__ w_ih,
                             const float* __restrict__ b_ih,
                             const float* __restrict__ b_hh) {
    const int v = blockIdx.x;
    __shared__ float es[EE];
    if (threadIdx.x < EE) es[threadIdx.x] = emb[v * EE + threadIdx.x];
    __syncthreads();
    for (int j = threadIdx.x; j < GG; j += blockDim.x) {
        float a = b_ih[j] + b_hh[j];
        const float* w = w_ih + (size_t)j * EE;
#pragma unroll 8
        for (int e = 0; e < EE; e++) a += es[e] * w[e];
        tab[(size_t)v * GG + j] = a;
    }
}

__global__ void misc_init_kernel(const int* __restrict__ trg,
                                 const float* __restrict__ be_ih1, const float* __restrict__ be_hh1,
                                 const float* __restrict__ bd_ih1, const float* __restrict__ bd_hh1,
                                 const float* __restrict__ fc_w) {
    const int tid = blockIdx.x * blockDim.x + threadIdx.x;
    const int n = gridDim.x * blockDim.x;
    for (int i = tid; i < HB; i += n) {
        g_h0TA[i] = 0.f; g_h0TB[i] = 0.f;
        g_h1TA[i] = 0.f; g_h1TB[i] = 0.f;
    }
    for (int j = tid; j < GG; j += n) {
        g_b1e[j] = be_ih1[j] + be_hh1[j];
        g_b1d[j] = bd_ih1[j] + bd_hh1[j];
    }
    for (int i = tid; i < HH * VV; i += n) {
        int k = i >> 8, v = i & 255;
        g_fcT[i] = fc_w[v * HH + k];
    }
    for (int b = tid; b < BB; b += n) g_tok[b] = trg[b * TT];
}

// ---------------- persistent kernel pieces ----------------
struct Smem {
    float* As;    // per-warp: 8 warps x 2 bufs x 64k x 16b = 16384 floats
    float* Ws0;   // [16][WPAD]
    float* Wsx;
    float* Wsh;
    float* gbuf;  // [16][130]
    float* cs0;   // [4][128]
    float* cs1;
    int*   tks;   // [128]
};

__device__ __forceinline__ void load_wslice(float* dst, const float* __restrict__ W, int u0) {
    for (int idx = threadIdx.x; idx < 16 * HH; idx += NTH) {
        int c = idx >> 9, k = idx & 511;
        int j = (c >> 2) * HH + u0 + (c & 3);
        dst[c * WPAD + k] = W[(size_t)j * HH + k];
    }
}

// stage one 64k x 16b chunk for this warp (4 KB) via cp.async
__device__ __forceinline__ void stage_warp(float* dst, const float* __restrict__ srcT,
                                           int lane, int w16) {
#pragma unroll
    for (int i = 0; i < 8; i++) {
        int idx = i * 32 + lane;            // 256 x 16B
        int k = idx >> 2, jq = idx & 3;
        cp16(dst + k * 16 + jq * 4, srcT + (size_t)k * 128 + w16 + jq * 4);
    }
}

// warp-autonomous 128x16 tile GEMM over K=512 (this warp: 16 rows x 16 cols,
// thread: 8 rows x 1 col). No CTA barriers inside.
__device__ __forceinline__ void mma512w(const float* __restrict__ srcT,
                                        const float* __restrict__ Wsm,
                                        float* wbuf, ull acc[4],
                                        int lane, int w16, int lrb8, int cg) {
    const float* wp = Wsm + cg * WPAD;
    stage_warp(wbuf, srcT, lane, w16);
    CP_COMMIT();
#pragma unroll 1
    for (int ch = 0; ch < 8; ch++) {
        const float* cur = wbuf + (ch & 1) * 1024;
        if (ch < 7) {
            stage_warp(wbuf + ((ch + 1) & 1) * 1024, srcT + (size_t)(ch + 1) * 64 * 128, lane, w16);
            CP_COMMIT();
            CP_WAIT1();
        } else {
            CP_WAIT0();
        }
        __syncwarp();
#pragma unroll
        for (int k4 = 0; k4 < 16; k4++) {
            float4 wv = *(const float4*)&wp[ch * 64 + k4 * 4];
            float wl0 = wv.x, wl1 = wv.y, wl2 = wv.z, wl3 = wv.w;
#pragma unroll
            for (int kk = 0; kk < 4; kk++) {
                int ko = k4 * 4 + kk;
                ulonglong2 qa = *(const ulonglong2*)&cur[ko * 16 + lrb8];
                ulonglong2 qb = *(const ulonglong2*)&cur[ko * 16 + lrb8 + 4];
                float w = (kk == 0) ? wl0 : (kk == 1) ? wl1 : (kk == 2) ? wl2 : wl3;
                ull w2 = pk2(w, w);
                fma2(acc[0], qa.x, w2);
                fma2(acc[1], qa.y, w2);
                fma2(acc[2], qb.x, w2);
                fma2(acc[3], qb.y, w2);
            }
        }
        __syncwarp();
    }
}

template<bool HAS_TOK, bool HAS_X, bool WRITE_PLAIN>
__device__ __forceinline__ void lstm_step_dev(const Smem& sm,
                                              const float* __restrict__ tab,
                                              const float* __restrict__ bias,
                                              const float* __restrict__ xT,
                                              const float* __restrict__ Wx,
                                              const float* __restrict__ hT,
                                              const float* __restrict__ Wh,
                                              float* __restrict__ cs,
                                              float* __restrict__ hT_out,
                                              float* __restrict__ h_plain,
                                              int u0) {
    const int tid  = threadIdx.x;
    const int lane = tid & 31;
    const int warp = tid >> 5;
    const int rg = tid >> 4, cg = tid & 15;
    const int r0 = rg * 8;
    const int lrb8 = (rg & 1) * 8;
    const int w16 = warp * 16;
    const int jc = (cg >> 2) * HH + u0 + (cg & 3);
    float* wbuf = sm.As + warp * 2048;

    ull acc[4];
    if (HAS_TOK) {
#pragma unroll
        for (int rp = 0; rp < 4; rp++) {
            int ta = sm.tks[r0 + 2 * rp];
            int tb = sm.tks[r0 + 2 * rp + 1];
            acc[rp] = pk2(tab[(size_t)ta * GG + jc], tab[(size_t)tb * GG + jc]);
        }
    } else {
        float bv = bias[jc];
        ull b2 = pk2(bv, bv);
#pragma unroll
        for (int rp = 0; rp < 4; rp++) acc[rp] = b2;
    }

    if (HAS_X) mma512w(xT, Wx, wbuf, acc, lane, w16, lrb8, cg);
    mma512w(hT, Wh, wbuf, acc, lane, w16, lrb8, cg);

#pragma unroll
    for (int rp = 0; rp < 4; rp++)
        *(ull*)&sm.gbuf[cg * 130 + r0 + 2 * rp] = acc[rp];
    __syncthreads();

    const int b = tid & 127;
    const int uu0 = tid >> 7;
#pragma unroll
    for (int p = 0; p < 2; p++) {
        int uu = uu0 + p * 2;
        float gi = sm.gbuf[(0 * 4 + uu) * 130 + b];
        float gf = sm.gbuf[(1 * 4 + uu) * 130 + b];
        float gg = sm.gbuf[(2 * 4 + uu) * 130 + b];
        float go = sm.gbuf[(3 * 4 + uu) * 130 + b];
        float cold = cs[uu * 128 + b];
        float ig = 1.f / (1.f + expf(-gi));
        float fg = 1.f / (1.f + expf(-gf));
        float og = 1.f / (1.f + expf(-go));
        float cn = fg * cold + ig * tanhf(gg);
        float hn = og * tanhf(cn);
        cs[uu * 128 + b] = cn;
        hT_out[(u0 + uu) * 128 + b] = hn;
        if (WRITE_PLAIN) h_plain[b * HH + u0 + uu] = hn;
    }
    __syncthreads();
}

__device__ __forceinline__ void fc_step(const Smem& sm, int t,
                                        const float* __restrict__ fc_b,
                                        float* __restrict__ out) {
    const int b = blockIdx.x;
    const int tid = threadIdx.x;
    float* h1s = sm.gbuf;
    float* rv = sm.gbuf + 512;
    int*   ri = (int*)(sm.gbuf + 512 + 256);

    *(float2*)&h1s[tid * 2] = *(const float2*)&g_h1[b * HH + tid * 2];
    __syncthreads();

    float acc = fc_b[tid];
#pragma unroll 8
    for (int k = 0; k < HH; k++) acc += h1s[k] * g_fcT[k * VV + tid];
    out[((size_t)b * DSTEPS + t) * VV + tid] = acc;
    rv[tid] = acc; ri[tid] = tid;
    __syncthreads();
    for (int offs = 128; offs > 0; offs >>= 1) {
        if (tid < offs) {
            float o = rv[tid + offs]; int oi = ri[tid + offs];
            if (o > rv[tid] || (o == rv[tid] && oi < ri[tid])) { rv[tid] = o; ri[tid] = oi; }
        }
        __syncthreads();
    }
    if (tid == 0) g_tok[b] = ri[0];
    __syncthreads();
}

// ---------------- the persistent kernel ----------------
__global__ void __launch_bounds__(NTH, 1)
seq2seq_persistent(const int* __restrict__ src,
                   const float* __restrict__ eWhh0,
                   const float* __restrict__ eWih1, const float* __restrict__ eWhh1,
                   const float* __restrict__ dWhh0,
                   const float* __restrict__ dWih1, const float* __restrict__ dWhh1,
                   const float* __restrict__ fc_b,
                   float* __restrict__ out) {
    extern __shared__ float smraw[];
    Smem sm;
    sm.As  = smraw;                    // 16384 floats
    sm.Ws0 = smraw + 16384;
    sm.Wsx = sm.Ws0 + 16 * WPAD;
    sm.Wsh = sm.Wsx + 16 * WPAD;
    sm.gbuf = sm.Wsh + 16 * WPAD;      // 16*130
    sm.cs0 = sm.gbuf + 16 * 130;
    sm.cs1 = sm.cs0 + 512;
    sm.tks = (int*)(sm.cs1 + 512);

    const int tid = threadIdx.x;
    const int u0 = blockIdx.x * 4;

    // preload all three encoder weight slices; zero both cell states
    load_wslice(sm.Ws0, eWhh0, u0);
    load_wslice(sm.Wsx, eWih1, u0);
    load_wslice(sm.Wsh, eWhh1, u0);
    for (int i = tid; i < 512; i += NTH) { sm.cs0[i] = 0.f; sm.cs1[i] = 0.f; }
    __syncthreads();

    // ===== fused encoder: L0 step tau + L1 step tau-1 per gbar interval =====
    const float* h0cur = g_h0TA;                 // zeros
    float* h1cur = g_h1TA;                       // zeros
    float* h1nxt = g_h1TB;
    for (int tau = 0; tau <= SS; tau++) {
        if (tau < SS) {
            if (tid < BB) sm.tks[tid] = src[tid * SS + tau];
            __syncthreads();
            float* yT = g_y0T + (size_t)tau * HB;
            lstm_step_dev<true, false, false>(sm, g_tabE, nullptr, nullptr, nullptr,
                                              h0cur, sm.Ws0, sm.cs0, yT, nullptr, u0);
            h0cur = yT;
        }
        if (tau >= 1) {
            const float* xT = g_y0T + (size_t)(tau - 1) * HB;
            lstm_step_dev<false, true, false>(sm, nullptr, g_b1e, xT, sm.Wsx,
                                              h1cur, sm.Wsh, sm.cs1, h1nxt, nullptr, u0);
            float* tt = h1cur; h1cur = h1nxt; h1nxt = tt;
        }
        gbar();
    }

    // ===== decoder =====
    load_wslice(sm.Ws0, dWhh0, u0);
    load_wslice(sm.Wsx, dWih1, u0);
    load_wslice(sm.Wsh, dWhh1, u0);
    __syncthreads();
    const float* h0cur2 = g_y0T + (size_t)(SS - 1) * HB;   // encoder L0 final h
    float* h0bufs[2] = { g_h0TA, g_h0TB };
    for (int t = 0; t < DSTEPS; t++) {
        if (tid < BB) sm.tks[tid] = g_tok[tid];
        __syncthreads();
        float* h0nxt = h0bufs[t & 1];
        lstm_step_dev<true, false, false>(sm, g_tabD, nullptr, nullptr, nullptr,
                                          h0cur2, sm.Ws0, sm.cs0, h0nxt, nullptr, u0);
        gbar();
        lstm_step_dev<false, true, true>(sm, nullptr, g_b1d, h0nxt, sm.Wsx,
                                         h1cur, sm.Wsh, sm.cs1, h1nxt, g_h1, u0);
        gbar();
        fc_step(sm, t, fc_b, out);
        gbar();
        h0cur2 = h0nxt;
        float* tt = h1cur; h1cur = h1nxt; h1nxt = tt;
    }
}

// ---------------- host launch ----------------
extern "C" void kernel_launch(void* const* d_in, const int* in_sizes, int n_in,
                              void* d_out, int out_size) {
    const int*   src       = (const int*)d_in[0];
    const int*   trg       = (const int*)d_in[1];
    const float* enc_emb   = (const float*)d_in[2];
    const float* enc_w_ih0 = (const float*)d_in[3];
    const float* enc_w_hh0 = (const float*)d_in[4];
    const float* enc_b_ih0 = (const float*)d_in[5];
    const float* enc_b_hh0 = (const float*)d_in[6];
    const float* enc_w_ih1 = (const float*)d_in[7];
    const float* enc_w_hh1 = (const float*)d_in[8];
    const float* enc_b_ih1 = (const float*)d_in[9];
    const float* enc_b_hh1 = (const float*)d_in[10];
    const float* dec_emb   = (const float*)d_in[11];
    const float* dec_w_ih0 = (const float*)d_in[12];
    const float* dec_w_hh0 = (const float*)d_in[13];
    const float* dec_b_ih0 = (const float*)d_in[14];
    const float* dec_b_hh0 = (const float*)d_in[15];
    const float* dec_w_ih1 = (const float*)d_in[16];
    const float* dec_w_hh1 = (const float*)d_in[17];
    const float* dec_b_ih1 = (const float*)d_in[18];
    const float* dec_b_hh1 = (const float*)d_in[19];
    const float* fc_w      = (const float*)d_in[20];
    const float* fc_b      = (const float*)d_in[21];
    float* out = (float*)d_out;

    float* tabE; cudaGetSymbolAddress((void**)&tabE, g_tabE);
    float* tabD; cudaGetSymbolAddress((void**)&tabD, g_tabD);

    static int smem_set = 0;
    const int SMEM_BYTES = (16384 + 3 * 16 * WPAD + 16 * 130 + 512 + 512 + 128) * 4;
    if (!smem_set) {
        cudaFuncSetAttribute(seq2seq_persistent,
                             cudaFuncAttributeMaxDynamicSharedMemorySize, SMEM_BYTES);
        smem_set = 1;
    }

    table_kernel<<<VV, 256>>>(tabE, enc_emb, enc_w_ih0, enc_b_ih0, enc_b_hh0);
    table_kernel<<<VV, 256>>>(tabD, dec_emb, dec_w_ih0, dec_b_ih0, dec_b_hh0);
    misc_init_kernel<<<256, 256>>>(trg, enc_b_ih1, enc_b_hh1, dec_b_ih1, dec_b_hh1, fc_w);

    seq2seq_persistent<<<NCTA, NTH, SMEM_BYTES>>>(
        src, enc_w_hh0, enc_w_ih1, enc_w_hh1,
        dec_w_hh0, dec_w_ih1, dec_w_hh1, fc_b, out);

    (void)in_sizes; (void)n_in; (void)out_size;
}

// round 7
// speedup vs baseline: 1.1900x; 1.1369x over previous
#include <cuda_runtime.h>
#include <cuda_bf16.h>
#include <math.h>

#define BB   128
#define SS   1024
#define TT   257
#define VV   256
#define EE   128
#define HH   512
#define GG   2048
#define DSTEPS 256
#define NCTA 128
#define NTH  512
#define WPAD 516
#define HB   (HH * BB)

typedef unsigned long long ull;

// ---------------- device globals ----------------
__device__ float g_tabE[VV * GG];
__device__ float g_tabD[VV * GG];
__device__ float g_b1e[GG];
__device__ float g_b1d[GG];
__device__ float g_fcT[HH * VV];                 // [k][v]
__device__ float g_y0T[(size_t)SS * HB];         // encoder L0 outputs, [s][u][b]
__device__ float g_h0TA[HB], g_h0TB[HB];
__device__ float g_h1TA[HB], g_h1TB[HB];
__device__ float g_h1[BB * HH];                  // plain layout for fc
__device__ int   g_tok[BB];
__device__ int   g_arrive;
__device__ int   g_gen;

// ---------------- helpers ----------------
__device__ __forceinline__ ull pk2(float lo, float hi) {
    ull r; asm("mov.b64 %0, {%1, %2};" : "=l"(r) : "f"(lo), "f"(hi)); return r;
}
__device__ __forceinline__ void fma2(ull& d, ull a, ull b) {
    asm("fma.rn.f32x2 %0, %1, %2, %0;" : "+l"(d) : "l"(a), "l"(b));
}
__device__ __forceinline__ void cp16(float* dst_smem, const float* src) {
    unsigned s = (unsigned)__cvta_generic_to_shared(dst_smem);
    asm volatile("cp.async.cg.shared.global [%0], [%1], 16;" :: "r"(s), "l"(src));
}
#define CP_COMMIT() asm volatile("cp.async.commit_group;")
#define CP_WAIT0()  asm volatile("cp.async.wait_group 0;")
#define CP_WAIT1()  asm volatile("cp.async.wait_group 1;")

__device__ __forceinline__ void gbar() {
    __syncthreads();
    if (threadIdx.x == 0) {
        volatile int* vgen = &g_gen;
        int gen = *vgen;
        __threadfence();
        int t = atomicAdd(&g_arrive, 1);
        if (t == NCTA - 1) {
            atomicExch(&g_arrive, 0);
            __threadfence();
            atomicAdd(&g_gen, 1);
        } else {
            while (*vgen == gen) { }
        }
        __threadfence();
    }
    __syncthreads();
}

// ---------------- init kernels ----------------
__global__ void table_kernel(float* __restrict__ tab,
                             const float* __restrict__ emb,
                             const float* __restrict__ w_ih,
                             const float* __restrict__ b_ih,
                             const float* __restrict__ b_hh) {
    const int v = blockIdx.x;
    __shared__ float es[EE];
    if (threadIdx.x < EE) es[threadIdx.x] = emb[v * EE + threadIdx.x];
    __syncthreads();
    for (int j = threadIdx.x; j < GG; j += blockDim.x) {
        float a = b_ih[j] + b_hh[j];
        const float* w = w_ih + (size_t)j * EE;
#pragma unroll 8
        for (int e = 0; e < EE; e++) a += es[e] * w[e];
        tab[(size_t)v * GG + j] = a;
    }
}

__global__ void misc_init_kernel(const int* __restrict__ trg,
                                 const float* __restrict__ be_ih1, const float* __restrict__ be_hh1,
                                 const float* __restrict__ bd_ih1, const float* __restrict__ bd_hh1,
                                 const float* __restrict__ fc_w) {
    const int tid = blockIdx.x * blockDim.x + threadIdx.x;
    const int n = gridDim.x * blockDim.x;
    for (int i = tid; i < HB; i += n) {
        g_h0TA[i] = 0.f; g_h0TB[i] = 0.f;
        g_h1TA[i] = 0.f; g_h1TB[i] = 0.f;
    }
    for (int j = tid; j < GG; j += n) {
        g_b1e[j] = be_ih1[j] + be_hh1[j];
        g_b1d[j] = bd_ih1[j] + bd_hh1[j];
    }
    for (int i = tid; i < HH * VV; i += n) {
        int k = i >> 8, v = i & 255;
        g_fcT[i] = fc_w[v * HH + k];
    }
    for (int b = tid; b < BB; b += n) g_tok[b] = trg[b * TT];
}

// ---------------- persistent kernel pieces ----------------
struct Smem {
    float* As;    // 16 warps x (2 bufs x 32k x 16b) = 16384 floats
    float* Ws0;   // [16][WPAD]
    float* Wsx;
    float* Wsh;
    float* gbuf;  // [2][16][130]
    float* cs0;   // [4][128]
    float* cs1;
    int*   tks;   // [128]
};

__device__ __forceinline__ void load_wslice(float* dst, const float* __restrict__ W, int u0) {
    for (int idx = threadIdx.x; idx < 16 * HH; idx += NTH) {
        int c = idx >> 9, k = idx & 511;
        int j = (c >> 2) * HH + u0 + (c & 3);
        dst[c * WPAD + k] = W[(size_t)j * HH + k];
    }
}

// stage one 32k x 16b chunk for this warp (2 KB) via cp.async
__device__ __forceinline__ void stage_warp(float* dst, const float* __restrict__ srcT,
                                           int kg, int lane, int w16) {
#pragma unroll
    for (int i = 0; i < 4; i++) {
        int idx = i * 32 + lane;            // 128 x 16B
        int k = idx >> 2, jq = idx & 3;
        cp16(dst + k * 16 + jq * 4, srcT + (size_t)(kg + k) * 128 + w16 + jq * 4);
    }
}

// warp-autonomous partial GEMM over 256 k (this warp's K-half of one matrix).
// warp: 16 rows x 16 cols, thread: 8 rows x 1 col.
__device__ __forceinline__ void mma256w(const float* __restrict__ srcT,
                                        const float* __restrict__ Wsm,
                                        float* wbuf, ull acc[4],
                                        int lane, int w16, int lrb8, int cg, int koff) {
    const float* wp = Wsm + cg * WPAD + koff;
    stage_warp(wbuf, srcT, koff, lane, w16);
    CP_COMMIT();
#pragma unroll 1
    for (int ch = 0; ch < 8; ch++) {
        const float* cur = wbuf + (ch & 1) * 512;
        if (ch < 7) {
            stage_warp(wbuf + ((ch + 1) & 1) * 512, srcT, koff + (ch + 1) * 32, lane, w16);
            CP_COMMIT();
            CP_WAIT1();
        } else {
            CP_WAIT0();
        }
        __syncwarp();
#pragma unroll
        for (int k4 = 0; k4 < 8; k4++) {
            float4 wv = *(const float4*)&wp[ch * 32 + k4 * 4];
#pragma unroll
            for (int kk = 0; kk < 4; kk++) {
                int ko = k4 * 4 + kk;
                ulonglong2 qa = *(const ulonglong2*)&cur[ko * 16 + lrb8];
                ulonglong2 qb = *(const ulonglong2*)&cur[ko * 16 + lrb8 + 4];
                float w = (kk == 0) ? wv.x : (kk == 1) ? wv.y : (kk == 2) ? wv.z : wv.w;
                ull w2 = pk2(w, w);
                fma2(acc[0], qa.x, w2);
                fma2(acc[1], qa.y, w2);
                fma2(acc[2], qb.x, w2);
                fma2(acc[3], qb.y, w2);
            }
        }
        __syncwarp();
    }
}

template<bool HAS_TOK, bool HAS_X, bool WRITE_PLAIN>
__device__ __forceinline__ void lstm_step_dev(const Smem& sm,
                                              const float* __restrict__ tab,
                                              const float* __restrict__ bias,
                                              const float* __restrict__ xT,
                                              const float* __restrict__ Wx,
                                              const float* __restrict__ hT,
                                              const float* __restrict__ Wh,
                                              float* __restrict__ cs,
                                              float* __restrict__ hT_out,
                                              float* __restrict__ h_plain,
                                              int u0) {
    const int tid  = threadIdx.x;
    const int lane = tid & 31;
    const int wg   = tid >> 8;            // K-half group: 0 or 1
    const int t8   = tid & 255;
    const int rg   = t8 >> 4, cg = t8 & 15;
    const int r0   = rg * 8;
    const int lrb8 = (rg & 1) * 8;
    const int w16  = ((t8 >> 5)) * 16;    // row offset of this warp's 16 rows
    const int koff = wg * 256;
    const int jc   = (cg >> 2) * HH + u0 + (cg & 3);
    float* wbuf = sm.As + (tid >> 5) * 1024;

    ull acc[4];
    if (wg == 0) {
        if (HAS_TOK) {
#pragma unroll
            for (int rp = 0; rp < 4; rp++) {
                int ta = sm.tks[r0 + 2 * rp];
                int tb = sm.tks[r0 + 2 * rp + 1];
                acc[rp] = pk2(tab[(size_t)ta * GG + jc], tab[(size_t)tb * GG + jc]);
            }
        } else {
            float bv = bias[jc];
            ull b2 = pk2(bv, bv);
#pragma unroll
            for (int rp = 0; rp < 4; rp++) acc[rp] = b2;
        }
    } else {
#pragma unroll
        for (int rp = 0; rp < 4; rp++) acc[rp] = 0ULL;
    }

    if (HAS_X) mma256w(xT, Wx, wbuf, acc, lane, w16, lrb8, cg, koff);
    mma256w(hT, Wh, wbuf, acc, lane, w16, lrb8, cg, koff);

#pragma unroll
    for (int rp = 0; rp < 4; rp++)
        *(ull*)&sm.gbuf[wg * 2080 + cg * 130 + r0 + 2 * rp] = acc[rp];
    __syncthreads();

    // 512 (b, uu) pairs, one per thread; add the two K-half partials
    const int b = tid & 127;
    const int uu = tid >> 7;
    {
        float gi = sm.gbuf[(0 * 4 + uu) * 130 + b] + sm.gbuf[2080 + (0 * 4 + uu) * 130 + b];
        float gf = sm.gbuf[(1 * 4 + uu) * 130 + b] + sm.gbuf[2080 + (1 * 4 + uu) * 130 + b];
        float gg = sm.gbuf[(2 * 4 + uu) * 130 + b] + sm.gbuf[2080 + (2 * 4 + uu) * 130 + b];
        float go = sm.gbuf[(3 * 4 + uu) * 130 + b] + sm.gbuf[2080 + (3 * 4 + uu) * 130 + b];
        float cold = cs[uu * 128 + b];
        float ig = 1.f / (1.f + expf(-gi));
        float fg = 1.f / (1.f + expf(-gf));
        float og = 1.f / (1.f + expf(-go));
        float cn = fg * cold + ig * tanhf(gg);
        float hn = og * tanhf(cn);
        cs[uu * 128 + b] = cn;
        hT_out[(u0 + uu) * 128 + b] = hn;
        if (WRITE_PLAIN) h_plain[b * HH + u0 + uu] = hn;
    }
    __syncthreads();
}

__device__ __forceinline__ void fc_step(const Smem& sm, int t,
                                        const float* __restrict__ fc_b,
                                        float* __restrict__ out) {
    const int b = blockIdx.x;
    const int tid = threadIdx.x;
    float* h1s  = sm.gbuf;              // 512
    float* part = sm.gbuf + 512;        // 512
    float* rv   = sm.gbuf + 1024;       // 256
    int*   ri   = (int*)(sm.gbuf + 1024 + 256);

    h1s[tid] = g_h1[b * HH + tid];
    __syncthreads();

    const int v = tid & 255;
    const int half = tid >> 8;
    float acc = half ? 0.f : fc_b[v];
    const int k0 = half * 256;
#pragma unroll 8
    for (int k = k0; k < k0 + 256; k++) acc += h1s[k] * g_fcT[k * VV + v];
    part[half * 256 + v] = acc;
    __syncthreads();

    if (tid < 256) {
        float tot = part[tid] + part[256 + tid];
        out[((size_t)b * DSTEPS + t) * VV + tid] = tot;
        rv[tid] = tot; ri[tid] = tid;
    }
    __syncthreads();
    for (int offs = 128; offs > 0; offs >>= 1) {
        if (tid < offs) {
            float o = rv[tid + offs]; int oi = ri[tid + offs];
            if (o > rv[tid] || (o == rv[tid] && oi < ri[tid])) { rv[tid] = o; ri[tid] = oi; }
        }
        __syncthreads();
    }
    if (tid == 0) g_tok[b] = ri[0];
    __syncthreads();
}

// ---------------- the persistent kernel ----------------
__global__ void __launch_bounds__(NTH, 1)
seq2seq_persistent(const int* __restrict__ src,
                   const float* __restrict__ eWhh0,
                   const float* __restrict__ eWih1, const float* __restrict__ eWhh1,
                   const float* __restrict__ dWhh0,
                   const float* __restrict__ dWih1, const float* __restrict__ dWhh1,
                   const float* __restrict__ fc_b,
                   float* __restrict__ out) {
    extern __shared__ float smraw[];
    Smem sm;
    sm.As  = smraw;                    // 16384
    sm.Ws0 = smraw + 16384;
    sm.Wsx = sm.Ws0 + 16 * WPAD;
    sm.Wsh = sm.Wsx + 16 * WPAD;
    sm.gbuf = sm.Wsh + 16 * WPAD;      // 2 x 16 x 130 = 4160
    sm.cs0 = sm.gbuf + 4160;
    sm.cs1 = sm.cs0 + 512;
    sm.tks = (int*)(sm.cs1 + 512);

    const int tid = threadIdx.x;
    const int u0 = blockIdx.x * 4;

    load_wslice(sm.Ws0, eWhh0, u0);
    load_wslice(sm.Wsx, eWih1, u0);
    load_wslice(sm.Wsh, eWhh1, u0);
    for (int i = tid; i < 512; i += NTH) { sm.cs0[i] = 0.f; sm.cs1[i] = 0.f; }
    __syncthreads();

    // ===== fused encoder: L0 step tau + L1 step tau-1 per gbar interval =====
    const float* h0cur = g_h0TA;
    float* h1cur = g_h1TA;
    float* h1nxt = g_h1TB;
    for (int tau = 0; tau <= SS; tau++) {
        if (tau < SS) {
            if (tid < BB) sm.tks[tid] = src[tid * SS + tau];
            __syncthreads();
            float* yT = g_y0T + (size_t)tau * HB;
            lstm_step_dev<true, false, false>(sm, g_tabE, nullptr, nullptr, nullptr,
                                              h0cur, sm.Ws0, sm.cs0, yT, nullptr, u0);
            h0cur = yT;
        }
        if (tau >= 1) {
            const float* xT = g_y0T + (size_t)(tau - 1) * HB;
            lstm_step_dev<false, true, false>(sm, nullptr, g_b1e, xT, sm.Wsx,
                                              h1cur, sm.Wsh, sm.cs1, h1nxt, nullptr, u0);
            float* tt = h1cur; h1cur = h1nxt; h1nxt = tt;
        }
        gbar();
    }

    // ===== decoder =====
    load_wslice(sm.Ws0, dWhh0, u0);
    load_wslice(sm.Wsx, dWih1, u0);
    load_wslice(sm.Wsh, dWhh1, u0);
    __syncthreads();
    const float* h0cur2 = g_y0T + (size_t)(SS - 1) * HB;
    float* h0bufs[2] = { g_h0TA, g_h0TB };
    for (int t = 0; t < DSTEPS; t++) {
        if (tid < BB) sm.tks[tid] = g_tok[tid];
        __syncthreads();
        float* h0nxt = h0bufs[t & 1];
        lstm_step_dev<true, false, false>(sm, g_tabD, nullptr, nullptr, nullptr,
                                          h0cur2, sm.Ws0, sm.cs0, h0nxt, nullptr, u0);
        gbar();
        lstm_step_dev<false, true, true>(sm, nullptr, g_b1d, h0nxt, sm.Wsx,
                                         h1cur, sm.Wsh, sm.cs1, h1nxt, g_h1, u0);
        gbar();
        fc_step(sm, t, fc_b, out);
        gbar();
        h0cur2 = h0nxt;
        float* tt = h1cur; h1cur = h1nxt; h1nxt = tt;
    }
}

// ---------------- host launch ----------------
extern "C" void kernel_launch(void* const* d_in, const int* in_sizes, int n_in,
                              void* d_out, int out_size) {
    const int*   src       = (const int*)d_in[0];
    const int*   trg       = (const int*)d_in[1];
    const float* enc_emb   = (const float*)d_in[2];
    const float* enc_w_ih0 = (const float*)d_in[3];
    const float* enc_w_hh0 = (const float*)d_in[4];
    const float* enc_b_ih0 = (const float*)d_in[5];
    const float* enc_b_hh0 = (const float*)d_in[6];
    const float* enc_w_ih1 = (const float*)d_in[7];
    const float* enc_w_hh1 = (const float*)d_in[8];
    const float* enc_b_ih1 = (const float*)d_in[9];
    const float* enc_b_hh1 = (const float*)d_in[10];
    const float* dec_emb   = (const float*)d_in[11];
    const float* dec_w_ih0 = (const float*)d_in[12];
    const float* dec_w_hh0 = (const float*)d_in[13];
    const float* dec_b_ih0 = (const float*)d_in[14];
    const float* dec_b_hh0 = (const float*)d_in[15];
    const float* dec_w_ih1 = (const float*)d_in[16];
    const float* dec_w_hh1 = (const float*)d_in[17];
    const float* dec_b_ih1 = (const float*)d_in[18];
    const float* dec_b_hh1 = (const float*)d_in[19];
    const float* fc_w      = (const float*)d_in[20];
    const float* fc_b      = (const float*)d_in[21];
    float* out = (float*)d_out;

    float* tabE; cudaGetSymbolAddress((void**)&tabE, g_tabE);
    float* tabD; cudaGetSymbolAddress((void**)&tabD, g_tabD);

    static int smem_set = 0;
    const int SMEM_BYTES = (16384 + 3 * 16 * WPAD + 4160 + 512 + 512 + 128) * 4;
    if (!smem_set) {
        cudaFuncSetAttribute(seq2seq_persistent,
                             cudaFuncAttributeMaxDynamicSharedMemorySize, SMEM_BYTES);
        smem_set = 1;
    }

    table_kernel<<<VV, 256>>>(tabE, enc_emb, enc_w_ih0, enc_b_ih0, enc_b_hh0);
    table_kernel<<<VV, 256>>>(tabD, dec_emb, dec_w_ih0, dec_b_ih0, dec_b_hh0);
    misc_init_kernel<<<256, 256>>>(trg, enc_b_ih1, enc_b_hh1, dec_b_ih1, dec_b_hh1, fc_w);

    seq2seq_persistent<<<NCTA, NTH, SMEM_BYTES>>>(
        src, enc_w_hh0, enc_w_ih1, enc_w_hh1,
        dec_w_hh0, dec_w_ih1, dec_w_hh1, fc_b, out);

    (void)in_sizes; (void)n_in; (void)out_size;
}